// round 11
// baseline (speedup 1.0000x reference)
#include <cuda_runtime.h>
#include <cuda_fp16.h>
#include <cstdint>

// ChebConv, commuted:
//   Agg[m=row*8+j, k] = sum_{e: rows[e]=row} vals[e] * xh[512*cols[e] + j*64 + k]
//   out[m*192 + q]    = sum_k Agg[m,k] * w[k*192+q] + bias[q&63]     (out is [16384,192])
// Stage 1: scatter edges + x->fp16. Stage 2: gather -> g_aggT (k-major).
// Stage 3: dense tiled GEMM [16384,64]@[64,192] + bias.
#define N_VERTEX 2048
#define NNZ_MAX  98304
#define KCOLS    192
#define M_TOT    16384
#define NSUB     4
#define SUB_CAP  48
#define SLOTS    (NSUB * SUB_CAP)
#define TP       12
#define X_ELEMS  3145728
#define SCAT_BLK 384
#define GM       32                  // GEMM rows per block

__device__ int    g_cnt[N_VERTEX * NSUB];
__device__ float2 g_edge[N_VERTEX * NSUB * SUB_CAP];
__device__ __align__(16) __half g_xh[X_ELEMS];          // 6MB fp16 x
__device__ __align__(16) float  g_aggT[64 * M_TOT];     // 4MB, k-major Agg

typedef unsigned long long u64;
__device__ __forceinline__ u64 pk2(float a, float b) {
    u64 r; asm("mov.b64 %0, {%1, %2};" : "=l"(r) : "f"(a), "f"(b)); return r;
}
__device__ __forceinline__ u64 fma2(u64 a, u64 b, u64 c) {
    u64 d; asm("fma.rn.f32x2 %0, %1, %2, %3;" : "=l"(d) : "l"(a), "l"(b), "l"(c)); return d;
}
__device__ __forceinline__ uint4 ldg_nc_na(const void* p) {
    uint4 v;
    asm("ld.global.nc.L1::no_allocate.v4.u32 {%0,%1,%2,%3}, [%4];"
        : "=r"(v.x), "=r"(v.y), "=r"(v.z), "=r"(v.w) : "l"(p));
    return v;
}

// Fused prepass: blocks [0,SCAT_BLK) bucket-scatter edges; the rest convert x->fp16.
__global__ void k_prep(const float* __restrict__ x,
                       const float* __restrict__ vals,
                       const int*   __restrict__ rows,
                       const int*   __restrict__ cols, int nnz) {
    if (blockIdx.x < SCAT_BLK) {
        int i = blockIdx.x * blockDim.x + threadIdx.x;
        if (i < nnz) {
            int r   = rows[i];
            int sub = i & (NSUB - 1);
            int p   = atomicAdd(&g_cnt[r * NSUB + sub], 1);
            if (p < SUB_CAP)
                g_edge[(r * NSUB + sub) * SUB_CAP + p] =
                    make_float2(vals[i], __int_as_float(cols[i] * 1024));
        }
    } else {
        int i = (blockIdx.x - SCAT_BLK) * blockDim.x + threadIdx.x;
        if (i < X_ELEMS / 8) {
            float4 v0 = reinterpret_cast<const float4*>(x)[2 * i];
            float4 v1 = reinterpret_cast<const float4*>(x)[2 * i + 1];
            __half2 h0 = __floats2half2_rn(v0.x, v0.y);
            __half2 h1 = __floats2half2_rn(v0.z, v0.w);
            __half2 h2 = __floats2half2_rn(v1.x, v1.y);
            __half2 h3 = __floats2half2_rn(v1.z, v1.w);
            uint4 p;
            p.x = *reinterpret_cast<unsigned*>(&h0);
            p.y = *reinterpret_cast<unsigned*>(&h1);
            p.z = *reinterpret_cast<unsigned*>(&h2);
            p.w = *reinterpret_cast<unsigned*>(&h3);
            reinterpret_cast<uint4*>(g_xh)[i] = p;
        }
    }
}

// Gather-aggregate (R8 phase 1), output k-major to g_aggT[k*16384 + row*8 + j].
__global__ __launch_bounds__(256) void k_gather() {
    __shared__ alignas(16) float sP[4][512];
    __shared__ alignas(16) float sT[64 * TP];
    __shared__ float2 sE[SLOTS];
    __shared__ int    sCnt[NSUB];

    const int row = blockIdx.x;
    const int tid = threadIdx.x;

    if (tid < NSUB) {
        int c = g_cnt[row * NSUB + tid];
        sCnt[tid] = (c > SUB_CAP) ? SUB_CAP : c;
        g_cnt[row * NSUB + tid] = 0;                 // restore invariant for replay
    }
    __syncthreads();
    const int c0 = sCnt[0], c1 = sCnt[1], c2 = sCnt[2], c3 = sCnt[3];
    const int deg = c0 + c1 + c2 + c3;               // <= 192

    if (tid < deg) {
        int b, pos;
        if      (tid < c0)           { b = 0; pos = tid; }
        else if (tid < c0 + c1)      { b = 1; pos = tid - c0; }
        else if (tid < c0 + c1 + c2) { b = 2; pos = tid - c0 - c1; }
        else                         { b = 3; pos = tid - c0 - c1 - c2; }
        sE[tid] = g_edge[(row * NSUB + b) * SUB_CAP + pos];
    }
    __syncthreads();

    {
        const int lane = tid & 63;                   // owns halfs 8*lane .. 8*lane+7
        const int grp  = tid >> 6;                   // 4 edge-groups
        float a0=0.f,a1=0.f,a2=0.f,a3=0.f,a4=0.f,a5=0.f,a6=0.f,a7=0.f;
        const char* xb = (const char*)g_xh + lane * 16;
        #pragma unroll 12
        for (int i = grp; i < deg; i += 4) {
            float2 ed = sE[i];
            uint4 d = ldg_nc_na(xb + __float_as_int(ed.y));
            float v = ed.x;
            float2 f0 = __half22float2(*reinterpret_cast<__half2*>(&d.x));
            float2 f1 = __half22float2(*reinterpret_cast<__half2*>(&d.y));
            float2 f2 = __half22float2(*reinterpret_cast<__half2*>(&d.z));
            float2 f3 = __half22float2(*reinterpret_cast<__half2*>(&d.w));
            a0 = fmaf(v, f0.x, a0); a1 = fmaf(v, f0.y, a1);
            a2 = fmaf(v, f1.x, a2); a3 = fmaf(v, f1.y, a3);
            a4 = fmaf(v, f2.x, a4); a5 = fmaf(v, f2.y, a5);
            a6 = fmaf(v, f3.x, a6); a7 = fmaf(v, f3.y, a7);
        }
        float* sp = &sP[grp][8 * lane];
        *(float4*)(sp)     = make_float4(a0, a1, a2, a3);
        *(float4*)(sp + 4) = make_float4(a4, a5, a6, a7);
    }
    __syncthreads();

    if (tid < 128) {                                 // merge 4 partials + transpose
        const int f = 4 * tid;
        float4 p0 = *(const float4*)&sP[0][f];
        float4 p1 = *(const float4*)&sP[1][f];
        float4 p2 = *(const float4*)&sP[2][f];
        float4 p3 = *(const float4*)&sP[3][f];
        const int j  = f >> 6;
        const int k0 = f & 63;
        sT[TP * k0 + j]       = (p0.x + p1.x) + (p2.x + p3.x);
        sT[TP * (k0 + 1) + j] = (p0.y + p1.y) + (p2.y + p3.y);
        sT[TP * (k0 + 2) + j] = (p0.z + p1.z) + (p2.z + p3.z);
        sT[TP * (k0 + 3) + j] = (p0.w + p1.w) + (p2.w + p3.w);
    }
    __syncthreads();

    if (tid < 64) {                                  // store k-major: 8 j's per k
        const int k = tid;
        float4 v0 = *(const float4*)&sT[TP * k];     // j=0..3 (16B aligned: 48k)
        float4 v1 = *(const float4*)&sT[TP * k + 4]; // j=4..7
        float* dst = &g_aggT[k * M_TOT + row * 8];
        *(float4*)(dst)     = v0;
        *(float4*)(dst + 4) = v1;
    }
}

// Tiled GEMM: [16384,64]@[64,192] + bias. 512 blocks x 256 thr, tile M=32.
// Thread = (mg 0..7: 4 rows, qg 0..31: 6 cols). A broadcast from smem, w from smem.
__global__ __launch_bounds__(256) void k_gemm(
    const float* __restrict__ w,
    const float* __restrict__ bias,
    float* __restrict__ out)
{
    __shared__ float sW[64 * KCOLS];                 // 48KB
    __shared__ alignas(16) float sA[64 * GM];        // 8KB, [k][m]
    const int tid = threadIdx.x;
    const int m0  = blockIdx.x * GM;

    for (int i = tid; i < 64 * KCOLS / 4; i += 256)
        ((float4*)sW)[i] = ((const float4*)w)[i];
    for (int i = tid; i < 64 * GM / 4; i += 256) {
        int k = i >> 3, part = i & 7;                // 8 float4 per k-row
        ((float4*)sA)[i] = *(const float4*)&g_aggT[k * M_TOT + m0 + 4 * part];
    }
    __syncthreads();

    const int mg = tid >> 5;                         // rows m0+4mg .. +3
    const int qg = tid & 31;                         // q = 6qg .. 6qg+5
    u64 acc[4][3];
    #pragma unroll
    for (int r = 0; r < 4; ++r)
        #pragma unroll
        for (int p = 0; p < 3; ++p) acc[r][p] = 0ull;

    const float* ap = sA + 4 * mg;
    const float* wp = sW + 6 * qg;
    #pragma unroll 4
    for (int k = 0; k < 64; ++k) {
        float4 a = *(const float4*)(ap + GM * k);    // LDS.128 broadcast in warp
        u64 w0 = *(const u64*)(wp + KCOLS * k);      // 8B-aligned (24B*qg)
        u64 w1 = *(const u64*)(wp + KCOLS * k + 2);
        u64 w2 = *(const u64*)(wp + KCOLS * k + 4);
        u64 d0 = pk2(a.x, a.x), d1 = pk2(a.y, a.y);
        u64 d2 = pk2(a.z, a.z), d3 = pk2(a.w, a.w);
        acc[0][0] = fma2(d0, w0, acc[0][0]); acc[0][1] = fma2(d0, w1, acc[0][1]); acc[0][2] = fma2(d0, w2, acc[0][2]);
        acc[1][0] = fma2(d1, w0, acc[1][0]); acc[1][1] = fma2(d1, w1, acc[1][1]); acc[1][2] = fma2(d1, w2, acc[1][2]);
        acc[2][0] = fma2(d2, w0, acc[2][0]); acc[2][1] = fma2(d2, w1, acc[2][1]); acc[2][2] = fma2(d2, w2, acc[2][2]);
        acc[3][0] = fma2(d3, w0, acc[3][0]); acc[3][1] = fma2(d3, w1, acc[3][1]); acc[3][2] = fma2(d3, w2, acc[3][2]);
    }

    const int qb = 6 * qg;
    float bv[6];
    #pragma unroll
    for (int i = 0; i < 6; ++i) bv[i] = __ldg(&bias[(qb + i) & 63]);
    float* op = out + (size_t)(m0 + 4 * mg) * KCOLS + qb;
    #pragma unroll
    for (int r = 0; r < 4; ++r) {
        #pragma unroll
        for (int p = 0; p < 3; ++p) {
            float lo, hi;
            asm("mov.b64 {%0, %1}, %2;" : "=f"(lo), "=f"(hi) : "l"(acc[r][p]));
            op[r * KCOLS + 2 * p]     = lo + bv[2 * p];
            op[r * KCOLS + 2 * p + 1] = hi + bv[2 * p + 1];
        }
    }
}

extern "C" void kernel_launch(void* const* d_in, const int* in_sizes, int n_in,
                              void* d_out, int out_size) {
    const float* x    = (const float*)d_in[0];
    const float* w    = (const float*)d_in[1];
    const float* bias = (const float*)d_in[2];
    const float* fv   = (const float*)d_in[3];
    const int*   fr   = (const int*)d_in[4];
    const int*   fc   = (const int*)d_in[5];
    int nnz = in_sizes[3];
    if (nnz > NNZ_MAX) nnz = NNZ_MAX;
    float* out = (float*)d_out;

    const int conv_blocks = (X_ELEMS / 8 + 255) / 256;   // 1536
    k_prep  <<<SCAT_BLK + conv_blocks, 256>>>(x, fv, fr, fc, nnz);
    k_gather<<<N_VERTEX, 256>>>();
    k_gemm  <<<M_TOT / GM, 256>>>(w, bias, out);
}

// round 13
// speedup vs baseline: 1.4576x; 1.4576x over previous
#include <cuda_runtime.h>
#include <cuda_fp16.h>
#include <cstdint>

// ChebConv, commuted:
//   Agg[row, j*64+k] = sum_{e: rows[e]=row} vals[e] * xh[512*cols[e] + j*64 + k]
//   out[(row*8+j)*192 + q] = sum_k Agg[row,j,k] * w[k*192+q] + bias[q&63]
// fp16 gather + fp16 HMMA phase 2 (m16n8k16, rows 8..15 zero), fp32 accumulation.
#define N_VERTEX 2048
#define NNZ_MAX  98304
#define KCOLS    192
#define NSUB     4
#define SUB_CAP  48
#define SLOTS    (NSUB * SUB_CAP)
#define X_ELEMS  3145728
#define SCAT_BLK 384
#define WFRAG_N  6144          // 24 ntw-groups * 32 lanes * 8 words
#define WFRAG_BLK 24           // 24 blocks x 256 threads = 6144 frag words
#define ASTR     72            // sAh row stride (halfs)

__device__ int    g_cnt[N_VERTEX * NSUB];
__device__ float2 g_edge[N_VERTEX * NSUB * SUB_CAP];
__device__ __align__(16) __half   g_xh[X_ELEMS];       // 6MB fp16 x
__device__ __align__(16) unsigned g_wfrag[WFRAG_N];    // 24KB precomputed B fragments

__device__ __forceinline__ uint4 ldg_nc_na(const void* p) {
    uint4 v;
    asm("ld.global.nc.L1::no_allocate.v4.u32 {%0,%1,%2,%3}, [%4];"
        : "=r"(v.x), "=r"(v.y), "=r"(v.z), "=r"(v.w) : "l"(p));
    return v;
}
__device__ __forceinline__ void mma16816(float& c0, float& c1, float& c2, float& c3,
                                         unsigned a0, unsigned a1, unsigned a2, unsigned a3,
                                         unsigned b0, unsigned b1) {
    asm volatile("mma.sync.aligned.m16n8k16.row.col.f32.f16.f16.f32 "
                 "{%0,%1,%2,%3}, {%4,%5,%6,%7}, {%8,%9}, {%0,%1,%2,%3};"
                 : "+f"(c0), "+f"(c1), "+f"(c2), "+f"(c3)
                 : "r"(a0), "r"(a1), "r"(a2), "r"(a3), "r"(b0), "r"(b1));
}

// Fused prepass: [0,384) edge scatter; [384,408) w B-fragment precompute; rest x->fp16.
__global__ void k_prep(const float* __restrict__ x,
                       const float* __restrict__ wf,
                       const float* __restrict__ vals,
                       const int*   __restrict__ rows,
                       const int*   __restrict__ cols, int nnz) {
    if (blockIdx.x < SCAT_BLK) {
        int i = blockIdx.x * blockDim.x + threadIdx.x;
        if (i < nnz) {
            int r   = rows[i];
            int sub = i & (NSUB - 1);
            int p   = atomicAdd(&g_cnt[r * NSUB + sub], 1);
            if (p < SUB_CAP)
                g_edge[(r * NSUB + sub) * SUB_CAP + p] =
                    make_float2(vals[i], __int_as_float(cols[i] * 1024));
        }
    } else if (blockIdx.x < SCAT_BLK + WFRAG_BLK) {
        // B fragment for mma.m16n8k16.row.col: thread holds {B[k][n], B[k+1][n]},
        // fid = ntw*256 + lane*8 + (2*kt + h); k = 16*kt + 8*h + 2*(lane&3),
        // n = 8*ntw + lane/4.   (ntw = warp*4 + nt in the consumer.)
        int fid  = (blockIdx.x - SCAT_BLK) * 256 + threadIdx.x;   // < 6144
        int r    = fid & 7;            // 2*kt + h
        int lane = (fid >> 3) & 31;
        int ntw  = fid >> 8;           // 0..23
        int kt   = r >> 1, h = r & 1;
        int k = 16 * kt + 8 * h + 2 * (lane & 3);
        int n = 8 * ntw + (lane >> 2);
        __half2 v = __floats2half2_rn(wf[k * KCOLS + n], wf[(k + 1) * KCOLS + n]);
        g_wfrag[fid] = *reinterpret_cast<unsigned*>(&v);
    } else {
        int i = (blockIdx.x - SCAT_BLK - WFRAG_BLK) * blockDim.x + threadIdx.x;
        if (i < X_ELEMS / 8) {
            float4 v0 = reinterpret_cast<const float4*>(x)[2 * i];
            float4 v1 = reinterpret_cast<const float4*>(x)[2 * i + 1];
            __half2 h0 = __floats2half2_rn(v0.x, v0.y);
            __half2 h1 = __floats2half2_rn(v0.z, v0.w);
            __half2 h2 = __floats2half2_rn(v1.x, v1.y);
            __half2 h3 = __floats2half2_rn(v1.z, v1.w);
            uint4 p;
            p.x = *reinterpret_cast<unsigned*>(&h0);
            p.y = *reinterpret_cast<unsigned*>(&h1);
            p.z = *reinterpret_cast<unsigned*>(&h2);
            p.w = *reinterpret_cast<unsigned*>(&h3);
            reinterpret_cast<uint4*>(g_xh)[i] = p;
        }
    }
}

// Fused per-row kernel: fp16 gather -> fp16 smem Agg -> HMMA phase 2.
__global__ __launch_bounds__(256) void k_main(
    const float* __restrict__ bias,
    float* __restrict__ out)
{
    __shared__ alignas(16) float  sP[4][512];           // gather partials (8KB)
    __shared__ alignas(16) __half sAh[8 * ASTR];        // fp16 Agg, rows j=0..7
    __shared__ float2 sE[SLOTS];
    __shared__ int    sCnt[NSUB];

    const int row = blockIdx.x;
    const int tid = threadIdx.x;

    if (tid < NSUB) {
        int c = g_cnt[row * NSUB + tid];
        sCnt[tid] = (c > SUB_CAP) ? SUB_CAP : c;
        g_cnt[row * NSUB + tid] = 0;                    // restore invariant for replay
    }
    __syncthreads();
    const int c0 = sCnt[0], c1 = sCnt[1], c2 = sCnt[2], c3 = sCnt[3];
    const int deg = c0 + c1 + c2 + c3;                  // <= 192

    if (tid < deg) {
        int b, pos;
        if      (tid < c0)           { b = 0; pos = tid; }
        else if (tid < c0 + c1)      { b = 1; pos = tid - c0; }
        else if (tid < c0 + c1 + c2) { b = 2; pos = tid - c0 - c1; }
        else                         { b = 3; pos = tid - c0 - c1 - c2; }
        sE[tid] = g_edge[(row * NSUB + b) * SUB_CAP + pos];
    }
    __syncthreads();

    // ---- Phase 1: fp16 gather; 64 lanes (8 halfs) x 4 edge-groups ----
    {
        const int lane = tid & 63;
        const int grp  = tid >> 6;
        float a0=0.f,a1=0.f,a2=0.f,a3=0.f,a4=0.f,a5=0.f,a6=0.f,a7=0.f;
        const char* xb = (const char*)g_xh + lane * 16;
        #pragma unroll 12
        for (int i = grp; i < deg; i += 4) {
            float2 ed = sE[i];
            uint4 d = ldg_nc_na(xb + __float_as_int(ed.y));
            float v = ed.x;
            float2 f0 = __half22float2(*reinterpret_cast<__half2*>(&d.x));
            float2 f1 = __half22float2(*reinterpret_cast<__half2*>(&d.y));
            float2 f2 = __half22float2(*reinterpret_cast<__half2*>(&d.z));
            float2 f3 = __half22float2(*reinterpret_cast<__half2*>(&d.w));
            a0 = fmaf(v, f0.x, a0); a1 = fmaf(v, f0.y, a1);
            a2 = fmaf(v, f1.x, a2); a3 = fmaf(v, f1.y, a3);
            a4 = fmaf(v, f2.x, a4); a5 = fmaf(v, f2.y, a5);
            a6 = fmaf(v, f3.x, a6); a7 = fmaf(v, f3.y, a7);
        }
        float* sp = &sP[grp][8 * lane];
        *(float4*)(sp)     = make_float4(a0, a1, a2, a3);
        *(float4*)(sp + 4) = make_float4(a4, a5, a6, a7);
    }
    __syncthreads();

    // merge 4 partials, convert to fp16: sAh[j*ASTR + k]
    if (tid < 128) {
        const int f = 4 * tid;
        float4 p0 = *(const float4*)&sP[0][f];
        float4 p1 = *(const float4*)&sP[1][f];
        float4 p2 = *(const float4*)&sP[2][f];
        float4 p3 = *(const float4*)&sP[3][f];
        const int j  = f >> 6;
        const int k0 = f & 63;
        __half2 h0 = __floats2half2_rn((p0.x+p1.x)+(p2.x+p3.x), (p0.y+p1.y)+(p2.y+p3.y));
        __half2 h1 = __floats2half2_rn((p0.z+p1.z)+(p2.z+p3.z), (p0.w+p1.w)+(p2.w+p3.w));
        uint2 pk;
        pk.x = *reinterpret_cast<unsigned*>(&h0);
        pk.y = *reinterpret_cast<unsigned*>(&h1);
        *reinterpret_cast<uint2*>(&sAh[j * ASTR + k0]) = pk;
    }
    __syncthreads();

    // ---- Phase 2: A[8(pad 16),64] @ W[64,192] via HMMA; warps 0-5, 32 cols each ----
    const int warp = tid >> 5;
    if (warp < 6) {
        const int lane = tid & 31;
        const int j    = lane >> 2;                     // output row (c0/c1 rows 0-7)
        const int l4   = lane & 3;

        unsigned afr[4][2];                             // [kt]: a0 (k 0-7), a2 (k 8-15)
        #pragma unroll
        for (int kt = 0; kt < 4; ++kt) {
            afr[kt][0] = *reinterpret_cast<const unsigned*>(&sAh[j * ASTR + kt * 16 + 2 * l4]);
            afr[kt][1] = *reinterpret_cast<const unsigned*>(&sAh[j * ASTR + kt * 16 + 8 + 2 * l4]);
        }

        float* orow = out + (size_t)(row * 8 + j) * KCOLS;
        #pragma unroll
        for (int nt = 0; nt < 4; ++nt) {
            const uint4* fp = reinterpret_cast<const uint4*>(
                &g_wfrag[((warp * 4 + nt) * 32 + lane) * 8]);
            uint4 blo = __ldg(fp);                      // kt=0: b0,b1; kt=1: b0,b1
            uint4 bhi = __ldg(fp + 1);                  // kt=2,3
            float acc0 = 0.f, acc1 = 0.f, acc2 = 0.f, acc3 = 0.f;
            mma16816(acc0, acc1, acc2, acc3, afr[0][0], 0u, afr[0][1], 0u, blo.x, blo.y);
            mma16816(acc0, acc1, acc2, acc3, afr[1][0], 0u, afr[1][1], 0u, blo.z, blo.w);
            mma16816(acc0, acc1, acc2, acc3, afr[2][0], 0u, afr[2][1], 0u, bhi.x, bhi.y);
            mma16816(acc0, acc1, acc2, acc3, afr[3][0], 0u, afr[3][1], 0u, bhi.z, bhi.w);
            const int q = 32 * warp + 8 * nt + 2 * l4;
            float b0 = __ldg(&bias[q & 63]);
            float b1 = __ldg(&bias[(q + 1) & 63]);
            *(float2*)(orow + q) = make_float2(acc0 + b0, acc1 + b1);
            // acc2/acc3 belong to padded rows 8-15: discarded.
        }
    }
}

extern "C" void kernel_launch(void* const* d_in, const int* in_sizes, int n_in,
                              void* d_out, int out_size) {
    const float* x    = (const float*)d_in[0];
    const float* w    = (const float*)d_in[1];
    const float* bias = (const float*)d_in[2];
    const float* fv   = (const float*)d_in[3];
    const int*   fr   = (const int*)d_in[4];
    const int*   fc   = (const int*)d_in[5];
    int nnz = in_sizes[3];
    if (nnz > NNZ_MAX) nnz = NNZ_MAX;
    float* out = (float*)d_out;

    const int conv_blocks = (X_ELEMS / 8 + 255) / 256;   // 1536
    k_prep<<<SCAT_BLK + WFRAG_BLK + conv_blocks, 256>>>(x, w, fv, fr, fc, nnz);
    k_main<<<N_VERTEX, 256>>>(bias, out);
}